// round 1
// baseline (speedup 1.0000x reference)
#include <cuda_runtime.h>

// Problem shapes (fixed by the dataset)
#define Bn 2
#define Vn 5
#define Cn 32
#define Hn 256
#define Wn 320
#define Dn 4
#define HWn (Hn*Wn)
#define NPTS (Bn*Dn*HWn)          // 655360 output points (b,d,h,w)
#define VAR_ELEMS (Bn*Cn*Dn*HWn)  // 20971520

// rot(9) + trans(3) per (b, v) for v=1..Vn-1
__device__ float g_rt[Bn*Vn*12];

// ---------------------------------------------------------------------------
// Prep: combine projections, invert ref, compute per-view rot/trans
// ---------------------------------------------------------------------------
__device__ __forceinline__ void combine_f32(const float* p, float M[4][4]) {
    // p: [2][4][4] = {extrinsic E, intrinsic K}
    const float* E = p;
    const float* K = p + 16;
    for (int i = 0; i < 4; i++)
        for (int j = 0; j < 4; j++)
            M[i][j] = E[i*4 + j];
    for (int i = 0; i < 3; i++)
        for (int j = 0; j < 4; j++) {
            float s = 0.f;
            for (int k = 0; k < 3; k++) s += K[i*4 + k] * E[k*4 + j];
            M[i][j] = s;
        }
}

__device__ void inv4x4(const float A[4][4], double X[4][4]) {
    double a[4][8];
    for (int i = 0; i < 4; i++) {
        for (int j = 0; j < 4; j++) {
            a[i][j] = (double)A[i][j];
            a[i][j+4] = (i == j) ? 1.0 : 0.0;
        }
    }
    for (int col = 0; col < 4; col++) {
        int piv = col; double best = fabs(a[col][col]);
        for (int r = col+1; r < 4; r++) {
            double v = fabs(a[r][col]);
            if (v > best) { best = v; piv = r; }
        }
        if (piv != col)
            for (int j = 0; j < 8; j++) { double t = a[col][j]; a[col][j] = a[piv][j]; a[piv][j] = t; }
        double d = 1.0 / a[col][col];
        for (int j = 0; j < 8; j++) a[col][j] *= d;
        for (int r = 0; r < 4; r++) {
            if (r == col) continue;
            double f = a[r][col];
            for (int j = 0; j < 8; j++) a[r][j] -= f * a[col][j];
        }
    }
    for (int i = 0; i < 4; i++)
        for (int j = 0; j < 4; j++) X[i][j] = a[i][j+4];
}

__global__ void prep_kernel(const float* __restrict__ proj) {
    if (threadIdx.x != 0 || blockIdx.x != 0) return;
    for (int b = 0; b < Bn; b++) {
        float Pr[4][4];
        combine_f32(proj + (size_t)(b*Vn + 0) * 32, Pr);
        double inv[4][4];
        inv4x4(Pr, inv);
        for (int v = 1; v < Vn; v++) {
            float Ps[4][4];
            combine_f32(proj + (size_t)(b*Vn + v) * 32, Ps);
            float* o = g_rt + (b*Vn + v) * 12;
            for (int i = 0; i < 3; i++) {
                double r0 = 0, r1 = 0, r2 = 0, t = 0;
                for (int k = 0; k < 4; k++) {
                    double s = (double)Ps[i][k];
                    r0 += s * inv[k][0];
                    r1 += s * inv[k][1];
                    r2 += s * inv[k][2];
                    t  += s * inv[k][3];
                }
                o[i*3 + 0] = (float)r0;
                o[i*3 + 1] = (float)r1;
                o[i*3 + 2] = (float)r2;
                o[9 + i]   = (float)t;
            }
        }
    }
}

// ---------------------------------------------------------------------------
// Zero the mask region (d_out is poisoned)
// ---------------------------------------------------------------------------
__global__ void zero_mask_kernel(float* __restrict__ outm) {
    int i = blockIdx.x * blockDim.x + threadIdx.x;
    if (i < Bn * HWn) outm[i] = 0.f;
}

// ---------------------------------------------------------------------------
// Main fused kernel: warp + bilinear + variance + mask
// One thread per (b, d, h, w); loops C channels.
// ---------------------------------------------------------------------------
__global__ void __launch_bounds__(256)
hammer_kernel(const float* __restrict__ feats,
              const float* __restrict__ depthv,
              float* __restrict__ outv,
              float* __restrict__ outm)
{
    int idx = blockIdx.x * blockDim.x + threadIdx.x;
    if (idx >= NPTS) return;

    int w = idx % Wn;
    int t = idx / Wn;
    int h = t % Hn; t /= Hn;
    int d = t % Dn;
    int b = t / Dn;

    const float dep = depthv[idx];
    const float xf = (float)w, yf = (float)h;

    int   off[4][4];
    float wt[4][4];
    int   basev[4];

    #pragma unroll
    for (int vi = 0; vi < 4; vi++) {
        const int v = vi + 1;
        const float* M = g_rt + (b*Vn + v) * 12;
        // rot @ (x, y, 1) * depth + trans
        float px = (M[0]*xf + M[1]*yf + M[2]) * dep + M[9];
        float py = (M[3]*xf + M[4]*yf + M[5]) * dep + M[10];
        float pz = (M[6]*xf + M[7]*yf + M[8]) * dep + M[11];
        float gx = px / pz;
        float gy = py / pz;

        float fx0 = floorf(gx), fy0 = floorf(gy);
        float ax = gx - fx0, ay = gy - fy0;
        int x0 = (int)fx0, y0 = (int)fy0;
        int x1 = x0 + 1,   y1 = y0 + 1;

        float w00 = (1.f - ax) * (1.f - ay);
        float w10 = ax * (1.f - ay);
        float w01 = (1.f - ax) * ay;
        float w11 = ax * ay;

        bool vx0 = (x0 >= 0) && (x0 < Wn);
        bool vx1 = (x1 >= 0) && (x1 < Wn);
        bool vy0 = (y0 >= 0) && (y0 < Hn);
        bool vy1 = (y1 >= 0) && (y1 < Hn);

        int xc0 = min(max(x0, 0), Wn - 1);
        int xc1 = min(max(x1, 0), Wn - 1);
        int yc0 = min(max(y0, 0), Hn - 1);
        int yc1 = min(max(y1, 0), Hn - 1);

        wt[vi][0] = (vx0 && vy0) ? w00 : 0.f;
        wt[vi][1] = (vx1 && vy0) ? w10 : 0.f;
        wt[vi][2] = (vx0 && vy1) ? w01 : 0.f;
        wt[vi][3] = (vx1 && vy1) ? w11 : 0.f;

        off[vi][0] = yc0*Wn + xc0;
        off[vi][1] = yc0*Wn + xc1;
        off[vi][2] = yc1*Wn + xc0;
        off[vi][3] = yc1*Wn + xc1;

        basev[vi] = (b*Vn + v) * Cn * HWn;
    }

    const int pix = h*Wn + w;
    const float* refp = feats + (size_t)(b*Vn) * Cn * HWn + pix;
    const int outbase = ((b*Cn) * Dn + d) * HWn + pix;

    unsigned nzmask = 0;
    const float invV = 1.0f / (float)Vn;

    #pragma unroll 4
    for (int c = 0; c < Cn; c++) {
        float rv = __ldg(refp + c*HWn);
        float s = rv;
        float q = rv * rv;
        #pragma unroll
        for (int vi = 0; vi < 4; vi++) {
            const float* p = feats + basev[vi] + c*HWn;
            float a0 = __ldg(p + off[vi][0]);
            float a1 = __ldg(p + off[vi][1]);
            float a2 = __ldg(p + off[vi][2]);
            float a3 = __ldg(p + off[vi][3]);
            float val = wt[vi][0]*a0 + wt[vi][1]*a1 + wt[vi][2]*a2 + wt[vi][3]*a3;
            if (val != 0.f) nzmask |= (1u << vi);
            s += val;
            q = fmaf(val, val, q);
        }
        float e = s * invV;
        outv[outbase + c * (Dn*HWn)] = fmaf(q, invV, -e*e);
    }

    int cnt = __popc(nzmask);
    if (cnt) atomicAdd(outm + b*HWn + pix, (float)cnt);
}

// ---------------------------------------------------------------------------
// Launch
// ---------------------------------------------------------------------------
extern "C" void kernel_launch(void* const* d_in, const int* in_sizes, int n_in,
                              void* d_out, int out_size)
{
    const float* feats  = (const float*)d_in[0];
    const float* proj   = (const float*)d_in[1];
    const float* depthv = (const float*)d_in[2];

    float* outv = (float*)d_out;
    float* outm = outv + VAR_ELEMS;

    zero_mask_kernel<<<(Bn*HWn + 255)/256, 256>>>(outm);
    prep_kernel<<<1, 1>>>(proj);
    hammer_kernel<<<(NPTS + 255)/256, 256>>>(feats, depthv, outv, outm);
}